// round 6
// baseline (speedup 1.0000x reference)
#include <cuda_runtime.h>
#include <cuda_bf16.h>
#include <math.h>

// Problem constants
#define B_    64
#define PANO_ 36
#define OBJ_  36
#define CFG_  16
#define LM_   8
#define IMG_  32
#define D_    300
#define H_    512
#define EMB_  64
#define ANG_  128
#define FEAT_ 2176
#define TOPN_ 3
#define M_    128          // CFG*LM
#define EPS_  1e-8f

// Output layout (flattened tuple): h_1 | c_1 | logit | h_tilde | ctx_attn
#define OFF_H1   0
#define OFF_C1   32768
#define OFF_LOG  65536
#define OFF_HT   67584
#define OFF_CA   100352

// ---------------- scratch (static device memory; no allocations) ----------------
__device__ float g_x[B_*3140];            // [action_emb(64) | attn_feat(3076)]
__device__ float g_qfeat[B_*3076];        // prev_h1 @ feat_in_W
__device__ int   g_top1[B_*3];
__device__ float g_nb1[B_*3];
__device__ int   g_top2[B_*3];
__device__ float g_nb2[B_*3];
__device__ float g_relmask[B_*3];
__device__ float g_landrel[B_*18];
__device__ float g_pano_sim[B_*PANO_*900];
__device__ float g_new_feat[B_*IMG_*921];
__device__ float g_a[B_*PANO_];
__device__ float g_p[B_*PANO_];
__device__ float g_gates[B_*2048];
__device__ float g_qa[B_*H_];
__device__ float g_cat[B_*1024];
__device__ float g_htp[B_*H_];
__device__ float g_q2[B_*3097];
__device__ float g_part[800000];          // split-K partials (max 4*64*3097)

// ---------------- helpers ----------------
__device__ __forceinline__ float wred(float v) {
    #pragma unroll
    for (int o = 16; o; o >>= 1) v += __shfl_down_sync(0xffffffffu, v, o);
    return v;
}
__device__ __forceinline__ float block_reduce(float v, float* sbuf) {
    int lane = threadIdx.x & 31, w = threadIdx.x >> 5;
    v = wred(v);
    if (lane == 0) sbuf[w] = v;
    __syncthreads();
    int nw = blockDim.x >> 5;
    v = (threadIdx.x < nw) ? sbuf[threadIdx.x] : 0.f;
    if (w == 0) v = wred(v);
    return v;   // valid on thread 0
}
__device__ __forceinline__ float sigmoidf_(float x) { return 1.f / (1.f + expf(-x)); }

// ---------------- action embedding: tanh(action @ emb_W + emb_b) -> g_x[:,0:64] ----------------
__global__ void k_action_embed(const float* __restrict__ action,
                               const float* __restrict__ embW,
                               const float* __restrict__ embB) {
    int idx = blockIdx.x * 128 + threadIdx.x;
    if (idx >= B_ * EMB_) return;
    int b = idx >> 6, e = idx & 63;
    float acc = embB[e];
    const float* a = action + b * ANG_;
    #pragma unroll 4
    for (int k = 0; k < ANG_; k++) acc += a[k] * embW[k * EMB_ + e];
    g_x[(size_t)b * 3140 + e] = tanhf(acc);
}

// ---------------- generic 64-row GEMM, split-K into partials ----------------
// part[y][b][j] = sum_{k in chunk y} A[b,k]*W[k,j];   C assembled by k_reduce
__global__ void k_gemm64(const float* __restrict__ A, int lda,
                         const float* __restrict__ W, int N,
                         int K, int kChunk, float* __restrict__ part) {
    int jb = blockIdx.x * 64;
    int k0 = blockIdx.y * kChunk;
    int kEnd = min(K, k0 + kChunk);
    __shared__ float sA[16][64];
    __shared__ float sW[16][64];
    int tid = threadIdx.x;             // 128 threads
    int tj = tid & 15, tb = tid >> 4;
    float acc[8][4];
    #pragma unroll
    for (int r = 0; r < 8; r++)
        #pragma unroll
        for (int c = 0; c < 4; c++) acc[r][c] = 0.f;
    int la_b = tid >> 1, la_k = (tid & 1) * 8;
    int lw_k = tid >> 3, lw_j = (tid & 7) * 8;
    for (int k = k0; k < kEnd; k += 16) {
        #pragma unroll
        for (int e = 0; e < 8; e++) {
            int kg = k + la_k + e;
            sA[la_k + e][la_b] = (kg < kEnd) ? A[(size_t)la_b * lda + kg] : 0.f;
        }
        int kg = k + lw_k;
        #pragma unroll
        for (int e = 0; e < 8; e++) {
            int jg = jb + lw_j + e;
            sW[lw_k][lw_j + e] = (kg < kEnd && jg < N) ? W[(size_t)kg * N + jg] : 0.f;
        }
        __syncthreads();
        #pragma unroll
        for (int kk = 0; kk < 16; kk++) {
            float av[8], wv[4];
            #pragma unroll
            for (int r = 0; r < 8; r++) av[r] = sA[kk][tb * 8 + r];
            #pragma unroll
            for (int c = 0; c < 4; c++) wv[c] = sW[kk][tj * 4 + c];
            #pragma unroll
            for (int r = 0; r < 8; r++)
                #pragma unroll
                for (int c = 0; c < 4; c++) acc[r][c] += av[r] * wv[c];
        }
        __syncthreads();
    }
    float* pp = part + (size_t)blockIdx.y * 64 * N;
    #pragma unroll
    for (int r = 0; r < 8; r++) {
        int b = tb * 8 + r;
        #pragma unroll
        for (int c = 0; c < 4; c++) {
            int j = jb + tj * 4 + c;
            if (j < N) pp[(size_t)b * N + j] = acc[r][c];
        }
    }
}

__global__ void k_reduce(const float* __restrict__ part, int S, int N,
                         const float* __restrict__ bias, float* __restrict__ C,
                         int accumulate) {
    int idx = blockIdx.x * 256 + threadIdx.x;
    int MN = 64 * N;
    if (idx >= MN) return;
    float v = accumulate ? C[idx] : 0.f;
    if (bias) v += bias[idx % N];
    for (int s = 0; s < S; s++) v += part[(size_t)s * MN + idx];
    C[idx] = v;
}

// ---------------- top-3 of score[b,cfg]*lmask[b,cfg,lm]; norms of selected land vecs ----------------
__global__ void k_topk(const float* __restrict__ score,   // [B,16]
                       const float* __restrict__ lmask,   // [B,128]
                       const float* __restrict__ land,    // [B,128,300]
                       const float* __restrict__ relmask_in, // [B,128] or null
                       const float* __restrict__ landrel_in, // [B,128,6] or null
                       int which) {
    int b = blockIdx.x;
    __shared__ float sv[128];
    __shared__ int sel[3];
    int tid = threadIdx.x;
    if (tid < 128) sv[tid] = score[b * 16 + (tid >> 3)] * lmask[b * 128 + tid];
    __syncthreads();
    int* top = which ? g_top2 : g_top1;
    float* nbout = which ? g_nb2 : g_nb1;
    if (tid < 32) {
        for (int r = 0; r < 3; r++) {
            float bv = -INFINITY; int bi = 128;
            for (int m = tid; m < 128; m += 32) {
                float v = sv[m];
                if (v > bv || (v == bv && m < bi)) { bv = v; bi = m; }
            }
            #pragma unroll
            for (int off = 16; off; off >>= 1) {
                float ov = __shfl_down_sync(0xffffffffu, bv, off);
                int   oi = __shfl_down_sync(0xffffffffu, bi, off);
                if (ov > bv || (ov == bv && oi < bi)) { bv = ov; bi = oi; }
            }
            if (tid == 0) { sel[r] = bi; top[b * 3 + r] = bi; sv[bi] = -INFINITY; }
            __syncwarp();
        }
    }
    __syncthreads();
    int w = tid >> 5, lane = tid & 31;
    if (w < 3) {
        int m = sel[w];
        const float* p = land + ((size_t)b * 128 + m) * D_;
        float s = 0.f;
        for (int d = lane; d < D_; d += 32) { float v = p[d]; s += v * v; }
        s = wred(s);
        if (lane == 0) nbout[b * 3 + w] = sqrtf(s);
    }
    if (relmask_in && tid < 3) {
        int m = sel[tid];
        g_relmask[b * 3 + tid] = relmask_in[b * 128 + m];
    }
    if (landrel_in && tid < 18) {
        int t = tid / 6, r2 = tid % 6;
        int m = sel[t];
        g_landrel[b * 18 + tid] = landrel_in[((size_t)b * 128 + m) * 6 + r2];
    }
}

// ---------------- object retrieval: argmax_o cos(obj[b,i,o], land[m_t]) + gather ----------------
__global__ void k_objret(const float* __restrict__ obj, int I, const float* __restrict__ land,
                         int which) {
    int bi = blockIdx.x;
    int b = bi / I;
    __shared__ float sl[3][D_];
    __shared__ float snb[3];
    __shared__ float ssim[OBJ_][3];
    __shared__ int sbest[3];
    int tid = threadIdx.x; // 256
    const int* top = which ? g_top2 : g_top1;
    const float* nb = which ? g_nb2 : g_nb1;
    for (int idx = tid; idx < 3 * D_; idx += 256) {
        int t = idx / D_, d = idx % D_;
        sl[t][d] = land[((size_t)b * 128 + top[b * 3 + t]) * D_ + d];
    }
    if (tid < 3) snb[tid] = nb[b * 3 + tid];
    __syncthreads();
    const float* ob = obj + (size_t)bi * OBJ_ * D_;
    int w = tid >> 5, lane = tid & 31;
    for (int o = w; o < OBJ_; o += 8) {
        const float* po = ob + o * D_;
        float d0 = 0.f, d1 = 0.f, d2 = 0.f, nr = 0.f;
        for (int d = lane; d < D_; d += 32) {
            float v = po[d];
            d0 += v * sl[0][d]; d1 += v * sl[1][d]; d2 += v * sl[2][d]; nr += v * v;
        }
        #pragma unroll
        for (int off = 16; off; off >>= 1) {
            d0 += __shfl_down_sync(0xffffffffu, d0, off);
            d1 += __shfl_down_sync(0xffffffffu, d1, off);
            d2 += __shfl_down_sync(0xffffffffu, d2, off);
            nr += __shfl_down_sync(0xffffffffu, nr, off);
        }
        if (lane == 0) {
            float na = sqrtf(nr);
            ssim[o][0] = d0 / fmaxf(na * snb[0], EPS_);
            ssim[o][1] = d1 / fmaxf(na * snb[1], EPS_);
            ssim[o][2] = d2 / fmaxf(na * snb[2], EPS_);
        }
    }
    __syncthreads();
    if (tid < 3) {
        float bv = -INFINITY; int bo = 0;
        for (int o = 0; o < OBJ_; o++) { float v = ssim[o][tid]; if (v > bv) { bv = v; bo = o; } }
        sbest[tid] = bo;
    }
    __syncthreads();
    float* out; int outStride, tStride;
    if (which) { out = g_new_feat; outStride = 921; tStride = 307; }
    else       { out = g_pano_sim; outStride = 900; tStride = 300; }
    float* po = out + (size_t)bi * outStride;
    for (int idx = tid; idx < 3 * D_; idx += 256) {
        int t = idx / D_, d = idx % D_;
        po[t * tStride + d] = ob[sbest[t] * D_ + d];
    }
}

// ---------------- feature attention ----------------
__global__ void k_feat_logits(const float* __restrict__ feature) {
    int bs = blockIdx.x; int b = bs / PANO_;
    __shared__ float sred[8];
    const float* f  = feature + (size_t)bs * FEAT_;
    const float* ps = g_pano_sim + (size_t)bs * 900;
    const float* qb = g_qfeat + (size_t)b * 3076;
    float acc = 0.f;
    for (int d = threadIdx.x; d < FEAT_; d += 128) acc += f[d] * qb[d];
    for (int d = threadIdx.x; d < 900;   d += 128) acc += ps[d] * qb[FEAT_ + d];
    acc = block_reduce(acc, sred);
    if (threadIdx.x == 0) g_a[bs] = acc;
}

__global__ void k_feat_softmax() {
    int b = blockIdx.x;
    __shared__ float s[PANO_];
    __shared__ float mx, sum;
    if (threadIdx.x < PANO_) s[threadIdx.x] = g_a[b * PANO_ + threadIdx.x];
    __syncthreads();
    if (threadIdx.x == 0) {
        float m = -INFINITY;
        for (int i = 0; i < PANO_; i++) m = fmaxf(m, s[i]);
        float su = 0.f;
        for (int i = 0; i < PANO_; i++) su += expf(s[i] - m);
        mx = m; sum = su;
    }
    __syncthreads();
    if (threadIdx.x < PANO_)
        g_p[b * PANO_ + threadIdx.x] = expf(s[threadIdx.x] - mx) / sum;
}

__global__ void k_attn_feat(const float* __restrict__ feature) {
    int b = blockIdx.y;
    int d = blockIdx.x * 256 + threadIdx.x;
    __shared__ float sp[PANO_];
    if (threadIdx.x < PANO_) sp[threadIdx.x] = g_p[b * PANO_ + threadIdx.x];
    __syncthreads();
    if (d >= 3076) return;
    float acc = 0.f;
    if (d < FEAT_) {
        const float* f = feature + (size_t)b * PANO_ * FEAT_ + d;
        #pragma unroll 4
        for (int s = 0; s < PANO_; s++) acc += sp[s] * f[(size_t)s * FEAT_];
    } else {
        const float* f = g_pano_sim + (size_t)b * PANO_ * 900 + (d - FEAT_);
        #pragma unroll 4
        for (int s = 0; s < PANO_; s++) acc += sp[s] * f[(size_t)s * 900];
    }
    g_x[(size_t)b * 3140 + 64 + d] = acc;
}

// ---------------- LSTM ----------------
__global__ void k_lstm(const float* __restrict__ c0, float* __restrict__ out) {
    int idx = blockIdx.x * 256 + threadIdx.x;
    if (idx >= B_ * H_) return;
    int b = idx >> 9, j = idx & 511;
    const float* g = g_gates + b * 2048;
    float ig = sigmoidf_(g[j]);
    float fg = sigmoidf_(g[512 + j]);
    float gg = tanhf(g[1024 + j]);
    float og = sigmoidf_(g[1536 + j]);
    float c1 = fg * c0[idx] + ig * gg;
    float h1 = og * tanhf(c1);
    out[OFF_H1 + idx] = h1;
    out[OFF_C1 + idx] = c1;
}

// ---------------- ctx attention (+softmax, wctx, cat) ----------------
__global__ void k_ctx_attn(const float* __restrict__ ctx, const unsigned char* __restrict__ cmask,
                           float* __restrict__ out) {
    int b = blockIdx.x;
    int tid = threadIdx.x; // 512
    __shared__ float sqa[H_], slg[CFG_], sattn[CFG_];
    sqa[tid] = g_qa[b * H_ + tid];
    __syncthreads();
    int w = tid >> 5, lane = tid & 31;
    const float* cb = ctx + (size_t)b * CFG_ * H_;
    {
        float acc = 0.f;
        const float* cw = cb + w * H_;
        for (int d = lane; d < H_; d += 32) acc += cw[d] * sqa[d];
        acc = wred(acc);
        if (lane == 0) slg[w] = cmask[b * CFG_ + w] ? -INFINITY : acc;
    }
    __syncthreads();
    if (tid == 0) {
        float m = -INFINITY;
        for (int s = 0; s < CFG_; s++) m = fmaxf(m, slg[s]);
        float su = 0.f;
        for (int s = 0; s < CFG_; s++) { float e = expf(slg[s] - m); sattn[s] = e; su += e; }
        float inv = 1.f / su;
        for (int s = 0; s < CFG_; s++) { sattn[s] *= inv; out[OFF_CA + b * CFG_ + s] = sattn[s]; }
    }
    __syncthreads();
    float acc = 0.f;
    #pragma unroll
    for (int s = 0; s < CFG_; s++) acc += sattn[s] * cb[(size_t)s * H_ + tid];
    g_cat[b * 1024 + tid] = acc;
    g_cat[b * 1024 + 512 + tid] = out[OFF_H1 + b * H_ + tid];
}

__global__ void k_tanh_ht(float* __restrict__ out) {
    int idx = blockIdx.x * 256 + threadIdx.x;
    if (idx >= B_ * H_) return;
    out[OFF_HT + idx] = tanhf(g_htp[idx]);
}

// ---------------- candidate relation features ----------------
__global__ void k_cand_rel(const float* __restrict__ crel) {
    int idx = blockIdx.x * 128 + threadIdx.x;
    if (idx >= B_ * IMG_ * 3) return;
    int t = idx % 3, bi = idx / 3;
    int b = bi / IMG_;
    const float* cr = crel + bi * 6;
    float rm = g_relmask[b * 3 + t];
    float* o = g_new_feat + (size_t)bi * 921 + t * 307 + 300;
    float dot = 0.f;
    #pragma unroll
    for (int r = 0; r < 6; r++) {
        float c = cr[r];
        o[r] = c * rm;
        dot += c * g_landrel[b * 18 + t * 6 + r];
    }
    o[6] = dot;
}

// ---------------- final logit ----------------
__global__ void k_logit(const float* __restrict__ candfeat, float* __restrict__ out) {
    int bi = blockIdx.x;
    int b = bi / IMG_;
    __shared__ float sred[8];
    const float* f  = candfeat + (size_t)bi * FEAT_;
    const float* nf = g_new_feat + (size_t)bi * 921;
    const float* q  = g_q2 + (size_t)b * 3097;
    float acc = 0.f;
    for (int d = threadIdx.x; d < FEAT_; d += 256) acc += f[d] * q[d];
    for (int d = threadIdx.x; d < 921;   d += 256) acc += nf[d] * q[FEAT_ + d];
    acc = block_reduce(acc, sred);
    if (threadIdx.x == 0) out[OFF_LOG + bi] = acc;
}

// ---------------- host launcher ----------------
extern "C" void kernel_launch(void* const* d_in, const int* in_sizes, int n_in,
                              void* d_out, int out_size) {
    const float* action    = (const float*)d_in[0];
    const float* feature   = (const float*)d_in[1];
    const float* cand_feat = (const float*)d_in[2];
    const float* prev_h1   = (const float*)d_in[3];
    const float* c_0       = (const float*)d_in[4];
    const float* ctx       = (const float*)d_in[5];
    const float* s_0       = (const float*)d_in[6];
    const float* land      = (const float*)d_in[7];
    const float* cand_obj  = (const float*)d_in[8];
    const float* lmask     = (const float*)d_in[9];
    const float* landrel   = (const float*)d_in[10];
    const float* relmask   = (const float*)d_in[11];
    const float* crel      = (const float*)d_in[12];
    const float* pano_obj  = (const float*)d_in[13];
    const float* embW      = (const float*)d_in[14];
    const float* embB      = (const float*)d_in[15];
    const float* W_ih      = (const float*)d_in[16];
    const float* W_hh      = (const float*)d_in[17];
    const float* b_lstm    = (const float*)d_in[18];
    const float* feat_in_W = (const float*)d_in[19];
    const float* att_in_W  = (const float*)d_in[20];
    const float* att_out_W = (const float*)d_in[21];
    const float* cand_in_W = (const float*)d_in[22];
    const unsigned char* cmask = (const unsigned char*)d_in[23];
    float* out = (float*)d_out;

    float *p_x, *p_qfeat, *p_gates, *p_qa, *p_cat, *p_htp, *p_q2, *p_part;
    cudaGetSymbolAddress((void**)&p_x,     g_x);
    cudaGetSymbolAddress((void**)&p_qfeat, g_qfeat);
    cudaGetSymbolAddress((void**)&p_gates, g_gates);
    cudaGetSymbolAddress((void**)&p_qa,    g_qa);
    cudaGetSymbolAddress((void**)&p_cat,   g_cat);
    cudaGetSymbolAddress((void**)&p_htp,   g_htp);
    cudaGetSymbolAddress((void**)&p_q2,    g_q2);
    cudaGetSymbolAddress((void**)&p_part,  g_part);

    // --- stage 1: independent prep ---
    k_action_embed<<<32, 128>>>(action, embW, embB);

    // q = prev_h1 @ feat_in_W  (64x3076, K=512, S=4)
    k_gemm64<<<dim3(49, 4), 128>>>(prev_h1, 512, feat_in_W, 3076, 512, 128, p_part);
    k_reduce<<<769, 256>>>(p_part, 4, 3076, nullptr, p_qfeat, 0);

    k_topk<<<B_, 128>>>(s_0, lmask, land, nullptr, nullptr, 0);
    k_objret<<<B_ * PANO_, 256>>>(pano_obj, PANO_, land, 0);

    // --- feature attention ---
    k_feat_logits<<<B_ * PANO_, 128>>>(feature);
    k_feat_softmax<<<B_, 64>>>();
    k_attn_feat<<<dim3(13, B_), 256>>>(feature);

    // --- LSTM gates: x@W_ih + h@W_hh + b ---
    k_gemm64<<<dim3(32, 5), 128>>>(p_x, 3140, W_ih, 2048, 3140, 640, p_part);
    k_reduce<<<512, 256>>>(p_part, 5, 2048, b_lstm, p_gates, 0);
    k_gemm64<<<dim3(32, 4), 128>>>(prev_h1, 512, W_hh, 2048, 512, 128, p_part);
    k_reduce<<<512, 256>>>(p_part, 4, 2048, nullptr, p_gates, 1);
    k_lstm<<<128, 256>>>(c_0, out);

    // --- ctx attention ---
    k_gemm64<<<dim3(8, 8), 128>>>(out + OFF_H1, 512, att_in_W, 512, 512, 64, p_part);
    k_reduce<<<128, 256>>>(p_part, 8, 512, nullptr, p_qa, 0);
    k_ctx_attn<<<B_, 512>>>(ctx, cmask, out);

    // h_tilde = tanh([wctx|h1] @ att_out_W)
    k_gemm64<<<dim3(8, 8), 128>>>(p_cat, 1024, att_out_W, 512, 1024, 128, p_part);
    k_reduce<<<128, 256>>>(p_part, 8, 512, nullptr, p_htp, 0);
    k_tanh_ht<<<128, 256>>>(out);

    // --- candidate retrieval ---
    k_topk<<<B_, 128>>>(out + OFF_CA, lmask, land, relmask, landrel, 1);
    k_objret<<<B_ * IMG_, 256>>>(cand_obj, IMG_, land, 1);
    k_cand_rel<<<48, 128>>>(crel);

    // q2 = h_tilde @ cand_in_W (64x3097, K=512, S=4)
    k_gemm64<<<dim3(49, 4), 128>>>(out + OFF_HT, 512, cand_in_W, 3097, 512, 128, p_part);
    k_reduce<<<775, 256>>>(p_part, 4, 3097, nullptr, p_q2, 0);

    k_logit<<<B_ * IMG_, 256>>>(cand_feat, out);
}